// round 1
// baseline (speedup 1.0000x reference)
#include <cuda_runtime.h>
#include <cstdint>
#include <cstddef>

// ---------------------------------------------------------------------------
// StructuredStateRecurrence: out = x + [x, scan(v)] @ Wg^T + bg
//   v = x @ Wv^T + bv ; scan: s_t = td*s_{t-1} + v_t ; wv = scan + ms*tf
//   next_memory_state = wv[:, -1]
// k = x@Wk+bk is dead code in the reference -> skipped.
// Shapes: B=4, S=4096, D=2048, M=512.
// ---------------------------------------------------------------------------

#define B_  4
#define S_  4096
#define D_  2048
#define M_  512
#define BSR (B_ * S_)        // 16384 GEMM rows
#define CCH 32               // scan chunks
#define LCH (S_ / CCH)       // 128 steps per chunk

// scratch (allocation-free rule: __device__ globals)
__device__ float g_wv[(size_t)B_ * S_ * M_];        // 33.5 MB
__device__ float g_carry[B_ * CCH * M_];
__device__ float g_prefix[B_ * CCH * M_];

__device__ __forceinline__ unsigned f2tf32(float f) {
    unsigned u;
    asm("cvt.rna.tf32.f32 %0, %1;" : "=r"(u) : "f"(f));
    return u;
}

__device__ __forceinline__ uint4 cvt4(float4 v) {
    return make_uint4(f2tf32(v.x), f2tf32(v.y), f2tf32(v.z), f2tf32(v.w));
}

__device__ __forceinline__ void mma_tf32(float (&c)[4], const unsigned (&a)[4],
                                         const unsigned (&b)[2]) {
    asm volatile(
        "mma.sync.aligned.m16n8k8.row.col.f32.tf32.tf32.f32 "
        "{%0,%1,%2,%3}, {%4,%5,%6,%7}, {%8,%9}, {%0,%1,%2,%3};\n"
        : "+f"(c[0]), "+f"(c[1]), "+f"(c[2]), "+f"(c[3])
        : "r"(a[0]), "r"(a[1]), "r"(a[2]), "r"(a[3]), "r"(b[0]), "r"(b[1]));
}

__device__ __forceinline__ float sigmoidf_(float t) {
    return 1.0f / (1.0f + expf(-t));
}

// ---------------------------------------------------------------------------
// TF32 GEMM: C[row, n] = sum_k A[row,k] * Bm[n,k] + bias[n] (+ resid[row,n])
// A is a virtual concat of A1 (K1 cols) and A2 (K2 cols); K-tiles never
// straddle the boundary (K1 % BK == 0 guaranteed by shapes).
// Block tile 128x128, BK=16, 256 threads, warp tile 64x32 (4x4 m16n8k8 frags).
// ---------------------------------------------------------------------------
template <bool HAS_A2, bool HAS_RES>
__global__ __launch_bounds__(256)
void gemm_tf32_kernel(const float* __restrict__ A1, int lda1, int K1,
                      const float* __restrict__ A2, int lda2, int K2,
                      const float* __restrict__ Bm,    // [N, K1+K2] row-major
                      const float* __restrict__ bias,  // [N]
                      const float* __restrict__ resid, int ldr,
                      float* __restrict__ Cout, int ldc)
{
    constexpr int BK = 16;
    constexpr int PAD = 20;  // words per smem row; conflict-free + 16B aligned
    __shared__ unsigned sA[2][128 * PAD];
    __shared__ unsigned sB[2][128 * PAD];

    const int tid = threadIdx.x;
    const int lane = tid & 31;
    const int warp = tid >> 5;
    const int wm = (warp & 1) * 64;   // warp row base in block tile
    const int wn = (warp >> 1) * 32;  // warp col base
    const int rowBlock = blockIdx.y * 128;
    const int colBlock = blockIdx.x * 128;
    const int Ktot = K1 + K2;

    // tile-load coordinates: 256 threads, each loads 2 float4 per tile side
    const int lr = tid >> 2;         // 0..63
    const int lc = (tid & 3) << 2;   // 0,4,8,12

    float acc[4][4][4];
#pragma unroll
    for (int i = 0; i < 4; ++i)
#pragma unroll
        for (int j = 0; j < 4; ++j)
#pragma unroll
            for (int q = 0; q < 4; ++q) acc[i][j][q] = 0.0f;

    auto gload = [&](int kBase, float4& ra0, float4& ra1, float4& rb0, float4& rb1) {
        const float* Ap = A1;
        int lda = lda1, kl = kBase;
        if (HAS_A2 && kBase >= K1) { Ap = A2; lda = lda2; kl = kBase - K1; }
        ra0 = *(const float4*)(Ap + (size_t)(rowBlock + lr) * lda + kl + lc);
        ra1 = *(const float4*)(Ap + (size_t)(rowBlock + lr + 64) * lda + kl + lc);
        rb0 = *(const float4*)(Bm + (size_t)(colBlock + lr) * Ktot + kBase + lc);
        rb1 = *(const float4*)(Bm + (size_t)(colBlock + lr + 64) * Ktot + kBase + lc);
    };
    auto sstore = [&](int buf, float4 ra0, float4 ra1, float4 rb0, float4 rb1) {
        *(uint4*)&sA[buf][lr * PAD + lc] = cvt4(ra0);
        *(uint4*)&sA[buf][(lr + 64) * PAD + lc] = cvt4(ra1);
        *(uint4*)&sB[buf][lr * PAD + lc] = cvt4(rb0);
        *(uint4*)&sB[buf][(lr + 64) * PAD + lc] = cvt4(rb1);
    };
    auto compute = [&](int buf) {
#pragma unroll
        for (int ks = 0; ks < 2; ++ks) {
            const int kk = ks * 8 + (lane & 3);
            unsigned a[4][4], bfr[4][2];
#pragma unroll
            for (int mi = 0; mi < 4; ++mi) {
                int r = wm + mi * 16 + (lane >> 2);
                a[mi][0] = sA[buf][r * PAD + kk];
                a[mi][1] = sA[buf][(r + 8) * PAD + kk];
                a[mi][2] = sA[buf][r * PAD + kk + 4];
                a[mi][3] = sA[buf][(r + 8) * PAD + kk + 4];
            }
#pragma unroll
            for (int ni = 0; ni < 4; ++ni) {
                int n = wn + ni * 8 + (lane >> 2);
                bfr[ni][0] = sB[buf][n * PAD + kk];
                bfr[ni][1] = sB[buf][n * PAD + kk + 4];
            }
#pragma unroll
            for (int mi = 0; mi < 4; ++mi)
#pragma unroll
                for (int ni = 0; ni < 4; ++ni) mma_tf32(acc[mi][ni], a[mi], bfr[ni]);
        }
    };

    const int KT = Ktot / BK;
    {
        float4 ra0, ra1, rb0, rb1;
        gload(0, ra0, ra1, rb0, rb1);
        sstore(0, ra0, ra1, rb0, rb1);
    }
    __syncthreads();

    int cur = 0;
    for (int kt = 0; kt < KT; ++kt) {
        float4 ra0, ra1, rb0, rb1;
        const bool pf = (kt + 1 < KT);
        if (pf) gload((kt + 1) * BK, ra0, ra1, rb0, rb1);
        compute(cur);
        if (pf) sstore(cur ^ 1, ra0, ra1, rb0, rb1);
        __syncthreads();
        cur ^= 1;
    }

    // epilogue: bias + optional residual, float2 stores (8B aligned: col even)
#pragma unroll
    for (int mi = 0; mi < 4; ++mi) {
#pragma unroll
        for (int ni = 0; ni < 4; ++ni) {
            const int row = rowBlock + wm + mi * 16 + (lane >> 2);
            const int col = colBlock + wn + ni * 8 + (lane & 3) * 2;
            const float b0v = bias[col];
            const float b1v = bias[col + 1];
            float r00 = 0.f, r01 = 0.f, r10 = 0.f, r11 = 0.f;
            if (HAS_RES) {
                const float2 q0 = *(const float2*)(resid + (size_t)row * ldr + col);
                const float2 q1 = *(const float2*)(resid + (size_t)(row + 8) * ldr + col);
                r00 = q0.x; r01 = q0.y; r10 = q1.x; r11 = q1.y;
            }
            *(float2*)(Cout + (size_t)row * ldc + col) =
                make_float2(acc[mi][ni][0] + b0v + r00, acc[mi][ni][1] + b1v + r01);
            *(float2*)(Cout + (size_t)(row + 8) * ldc + col) =
                make_float2(acc[mi][ni][2] + b0v + r10, acc[mi][ni][3] + b1v + r11);
        }
    }
}

// ---------------------------------------------------------------------------
// Scan pass A: per-chunk local scan (in place), emit chunk-end carry.
// grid (CCH, B_), 512 threads over m -> fully coalesced (consecutive m).
// ---------------------------------------------------------------------------
__global__ __launch_bounds__(M_)
void scan_local_kernel(const float* __restrict__ td_raw)
{
    const int m = threadIdx.x;
    const int c = blockIdx.x;
    const int b = blockIdx.y;
    const float td = sigmoidf_(td_raw[m]) * 0.9f + 0.1f;
    size_t base = ((size_t)(b * S_ + c * LCH)) * M_ + m;
    float s = 0.0f;
#pragma unroll 4
    for (int i = 0; i < LCH; ++i) {
        const float v = g_wv[base + (size_t)i * M_];
        s = fmaf(td, s, v);
        g_wv[base + (size_t)i * M_] = s;
    }
    g_carry[(b * CCH + c) * M_ + m] = s;
}

// Pass B: sequential carry scan across chunks (tiny: B_*M_ threads, CCH iters)
__global__ __launch_bounds__(M_)
void scan_carry_kernel(const float* __restrict__ td_raw)
{
    const int m = threadIdx.x;
    const int b = blockIdx.x;
    const float td = sigmoidf_(td_raw[m]) * 0.9f + 0.1f;
    const float tdL = powf(td, (float)LCH);
    float G = 0.0f;
    for (int c = 0; c < CCH; ++c) {
        const int idx = (b * CCH + c) * M_ + m;
        g_prefix[idx] = G;
        G = fmaf(tdL, G, g_carry[idx]);
    }
}

// Pass C: wv = local + P*td^(i+1) + ms*tf ; emit next_memory_state at t=S-1
__global__ __launch_bounds__(M_)
void scan_apply_kernel(const float* __restrict__ td_raw,
                       const float* __restrict__ tf_raw,
                       const float* __restrict__ ms,
                       float* __restrict__ nms)
{
    const int m = threadIdx.x;
    const int c = blockIdx.x;
    const int b = blockIdx.y;
    const float td = sigmoidf_(td_raw[m]) * 0.9f + 0.1f;
    const float tf = sigmoidf_(tf_raw[m]);
    const float msterm = ms[b * M_ + m] * tf;
    const float P = g_prefix[(b * CCH + c) * M_ + m];
    size_t base = ((size_t)(b * S_ + c * LCH)) * M_ + m;
    float pw = td;
    float w = 0.0f;
#pragma unroll 4
    for (int i = 0; i < LCH; ++i) {
        w = g_wv[base + (size_t)i * M_] + P * pw + msterm;
        g_wv[base + (size_t)i * M_] = w;
        pw *= td;
    }
    if (nms != nullptr && c == CCH - 1) nms[b * M_ + m] = w;
}

// ---------------------------------------------------------------------------
extern "C" void kernel_launch(void* const* d_in, const int* in_sizes, int n_in,
                              void* d_out, int out_size)
{
    const float* x   = (const float*)d_in[0];
    const float* ms  = (const float*)d_in[1];
    // d_in[2]=Wk, d_in[3]=bk: dead in the reference, intentionally unused
    const float* Wv  = (const float*)d_in[4];
    const float* bv  = (const float*)d_in[5];
    const float* Wg  = (const float*)d_in[6];
    const float* bg  = (const float*)d_in[7];
    const float* tdr = (const float*)d_in[8];
    const float* tfr = (const float*)d_in[9];
    float* out = (float*)d_out;

    float* wv_ptr = nullptr;
    cudaGetSymbolAddress((void**)&wv_ptr, g_wv);

    // 1) v = x @ Wv^T + bv  -> g_wv   [16384 x 512], K=2048
    dim3 g1(M_ / 128, BSR / 128);
    gemm_tf32_kernel<false, false><<<g1, 256>>>(
        x, D_, D_, nullptr, 0, 0, Wv, bv, nullptr, 0, wv_ptr, M_);

    // 2) linear recurrence (chunked scan) + ms*tf, emits next_memory_state
    const size_t bsd = (size_t)B_ * S_ * D_;
    float* nms = ((size_t)out_size >= bsd + (size_t)B_ * M_) ? out + bsd : nullptr;
    scan_local_kernel<<<dim3(CCH, B_), M_>>>(tdr);
    scan_carry_kernel<<<B_, M_>>>(tdr);
    scan_apply_kernel<<<dim3(CCH, B_), M_>>>(tdr, tfr, ms, nms);

    // 3) out = x + [x | wv] @ Wg^T + bg   [16384 x 2048], K=2560 split 2048+512
    dim3 g2(D_ / 128, BSR / 128);
    gemm_tf32_kernel<true, true><<<g2, 256>>>(
        x, D_, D_, wv_ptr, M_, M_, Wg, bg, x, D_, out, D_);
}